// round 14
// baseline (speedup 1.0000x reference)
#include <cuda_runtime.h>
#include <cuda_fp16.h>
#include <math.h>
#include <stdint.h>

// ConvEncoder: y = GELU(im2col(emb[x]) @ W^T + b).  M=32768, N=128, K=640.
// R14: single-pass fp16, tanh GELU. TOK=128, 512 thr, 16 warps of 32x32
// tiles (~90 regs -> scheduling headroom). FULL W (174KB) resident in smem:
// stage once, ONE sync, then a 40-kstep mainloop with ZERO barriers.
// Grid 256 CTAs (2 tight waves).

#define CE_S    2048
#define CE_KTOT 640
#define THREADS 512
#define TOK     128
#define ROW_B   272                  // fp16 row: 256B data + 16B pad (A and W)

// smem layout (bytes)
#define SA      0                    // 132 rows * 272 = 35904
#define SW      35904                // 5 * 128 * 272 = 174080
#define SBIAS   209984
#define SIDX    210496               // 132 ints
#define SM_TOT  211072

// W pre-converted fp16: [kc(5)][o(128)][272B]
__device__ __align__(16) unsigned char g_Wcvt[5 * 128 * ROW_B];

// GELU, tanh form with HW MUFU tanh
__device__ __forceinline__ float gelu_fast(float x) {
    float t = x * fmaf(0.03567740814f, x * x, 0.79788456080f);
    float th;
    asm("tanh.approx.f32 %0, %1;" : "=f"(th) : "f"(t));
    float h = 0.5f * x;
    return fmaf(h, th, h);
}

__device__ __forceinline__ void mma_f16(float* c, const uint32_t* a, const uint32_t* b) {
    asm volatile(
        "mma.sync.aligned.m16n8k16.row.col.f32.f16.f16.f32 "
        "{%0,%1,%2,%3}, {%4,%5,%6,%7}, {%8,%9}, {%0,%1,%2,%3};"
        : "+f"(c[0]), "+f"(c[1]), "+f"(c[2]), "+f"(c[3])
        : "r"(a[0]), "r"(a[1]), "r"(a[2]), "r"(a[3]), "r"(b[0]), "r"(b[1]));
}

__device__ __forceinline__ void ldsm4(uint32_t* r, uint32_t addr) {
    asm volatile("ldmatrix.sync.aligned.m8n8.x4.shared.b16 {%0,%1,%2,%3}, [%4];"
                 : "=r"(r[0]), "=r"(r[1]), "=r"(r[2]), "=r"(r[3]) : "r"(addr));
}

__device__ __forceinline__ void cpasync16(uint32_t dst, const void* src) {
    asm volatile("cp.async.cg.shared.global [%0], [%1], 16;"
                 :: "r"(dst), "l"(src) : "memory");
}

// convert 8 f32 -> 8 fp16 packed as uint4 (16 bytes)
__device__ __forceinline__ uint4 cvt8_f16(float4 v0, float4 v1) {
    union { __half2 h[4]; uint4 u; } p;
    p.h[0] = __float22half2_rn(make_float2(v0.x, v0.y));
    p.h[1] = __float22half2_rn(make_float2(v0.z, v0.w));
    p.h[2] = __float22half2_rn(make_float2(v1.x, v1.y));
    p.h[3] = __float22half2_rn(make_float2(v1.z, v1.w));
    return p.u;
}

// ---- prep: W f32 -> fp16, chunked layout for direct cp.async ----
__global__ void __launch_bounds__(256)
prep_w_kernel(const float* __restrict__ W)
{
    int t = blockIdx.x * 256 + threadIdx.x;        // 5*128*16 = 10240 granules
    if (t >= 5 * 128 * 16) return;
    int gnl = t & 15;
    int o   = (t >> 4) & 127;
    int kc  = t >> 11;
    const float* src = W + (size_t)o * CE_KTOT + kc * 128 + gnl * 8;
    float4 v0 = *reinterpret_cast<const float4*>(src);
    float4 v1 = *reinterpret_cast<const float4*>(src + 4);
    *reinterpret_cast<uint4*>(g_Wcvt + ((size_t)kc * 128 + o) * ROW_B + gnl * 16)
        = cvt8_f16(v0, v1);
}

__global__ void __launch_bounds__(THREADS)
conv_encoder_hmma(const int* __restrict__ x,
                  const float* __restrict__ emb,
                  const float* __restrict__ bias,
                  float* __restrict__ out)
{
    extern __shared__ uint8_t smem[];
    uint32_t sb;
    asm("{ .reg .u64 t; cvta.to.shared.u64 t, %1; cvt.u32.u64 %0, t; }"
        : "=r"(sb) : "l"(smem));

    const int tid = threadIdx.x;
    const int wid = tid >> 5;
    const int lid = tid & 31;
    const int g   = lid >> 2;
    const int q   = lid & 3;
    const int wm  = wid >> 2;       // 0..3  (32-row band within 128)
    const int wn  = wid & 3;        // 0..3  (32-col band)
    const int batch = blockIdx.y;
    const int s0 = blockIdx.x * TOK;

    // ---- stage entire W (174080 B) via cp.async: straight linear copy ----
    #pragma unroll
    for (int it = 0; it < 22; ++it) {
        int idx = tid + it * THREADS;              // 10880 granules of 16B
        if (idx < 5 * 128 * (ROW_B / 16))
            cpasync16(sb + SW + idx * 16, g_Wcvt + (size_t)idx * 16);
    }
    asm volatile("cp.async.commit_group;" ::: "memory");

    if (tid < 32) {
        reinterpret_cast<float4*>(smem + SBIAS)[tid] =
            reinterpret_cast<const float4*>(bias)[tid];
    }
    // token index cache: halo rows p=0..131 -> seq s0+p-2 (or -1 if OOB)
    if (tid < 132) {
        int s = s0 + tid - 2;
        reinterpret_cast<int*>(smem + SIDX)[tid] =
            (s >= 0 && s < CE_S) ? x[batch * CE_S + s] : -1;
    }
    __syncthreads();

    // ---- gather halo'd A: rows p=0..131, fp16 (132*16 = 2112 granules) ----
    #pragma unroll
    for (int it = 0; it < 5; ++it) {
        int idx = tid + it * THREADS;
        if (idx < 132 * 16) {
            int p = idx >> 4;
            int c = idx & 15;                      // 16B fp16 granule = 8 elems
            int tok = reinterpret_cast<const int*>(smem + SIDX)[p];
            float4 v0 = make_float4(0.f, 0.f, 0.f, 0.f);
            float4 v1 = v0;
            if (tok >= 0) {
                const float* e = emb + (size_t)tok * 128 + c * 8;
                v0 = *reinterpret_cast<const float4*>(e);
                v1 = *reinterpret_cast<const float4*>(e + 4);
            }
            *reinterpret_cast<uint4*>(smem + SA + p * ROW_B + c * 16) = cvt8_f16(v0, v1);
        }
    }
    asm volatile("cp.async.wait_group 0;" ::: "memory");
    __syncthreads();

    float acc[2][4][4];
    #pragma unroll
    for (int i = 0; i < 2; ++i)
        #pragma unroll
        for (int j = 0; j < 4; ++j)
            #pragma unroll
            for (int r = 0; r < 4; ++r)
                acc[i][j][r] = 0.f;

    // per-lane ldmatrix offsets
    const uint32_t a_off = ((lid & 7) + ((lid >> 3) & 1) * 8) * ROW_B + (lid >> 4) * 16;
    // B (x4, j-paired): lanes 0-15 -> n-tile jp (k halves), 16-31 -> n-tile jp+1
    const uint32_t b_off = ((lid & 7) + (lid >> 4) * 8) * ROW_B + ((lid >> 3) & 1) * 16;

    // ---- 5 chunks x 8 k-steps, ZERO barriers ----
    #pragma unroll
    for (int kc = 0; kc < 5; ++kc) {
        const uint32_t aA = sb + SA + (wm * 32 + kc) * ROW_B + a_off;
        const uint32_t aB = sb + SW + kc * (128 * ROW_B) + wn * 32 * ROW_B + b_off;
        #pragma unroll
        for (int ks = 0; ks < 8; ++ks) {
            const uint32_t kb = ks * 32;
            uint32_t Aa[2][4], Bb[2][4];
            ldsm4(Aa[0], aA + kb);
            ldsm4(Aa[1], aA + 16 * ROW_B + kb);
            ldsm4(Bb[0], aB + kb);
            ldsm4(Bb[1], aB + 16 * ROW_B + kb);
            #pragma unroll
            for (int i = 0; i < 2; ++i)
                #pragma unroll
                for (int j = 0; j < 4; ++j)
                    mma_f16(acc[i][j], Aa[i], &Bb[j >> 1][(j & 1) * 2]);
        }
    }

    // ---- epilogue: bias + fast GELU + store ----
    const float* bs = reinterpret_cast<const float*>(smem + SBIAS);
    #pragma unroll
    for (int i = 0; i < 2; ++i) {
        int row0 = s0 + wm * 32 + i * 16 + g;
        #pragma unroll
        for (int j = 0; j < 4; ++j) {
            int col = wn * 32 + j * 8 + q * 2;
            float b0 = bs[col], b1 = bs[col + 1];
            float2 v0, v1;
            v0.x = gelu_fast(acc[i][j][0] + b0);
            v0.y = gelu_fast(acc[i][j][1] + b1);
            v1.x = gelu_fast(acc[i][j][2] + b0);
            v1.y = gelu_fast(acc[i][j][3] + b1);
            float* p0 = out + ((size_t)(batch * CE_S + row0)) * 128 + col;
            *reinterpret_cast<float2*>(p0) = v0;
            *reinterpret_cast<float2*>(p0 + 8 * 128) = v1;
        }
    }
}

extern "C" void kernel_launch(void* const* d_in, const int* in_sizes, int n_in,
                              void* d_out, int out_size)
{
    const int*   x    = (const int*)  d_in[0];
    const float* emb  = (const float*)d_in[1];
    const float* W    = (const float*)d_in[2];
    const float* bias = (const float*)d_in[3];
    float*       out  = (float*)d_out;

    prep_w_kernel<<<40, 256>>>(W);

    cudaFuncSetAttribute(conv_encoder_hmma,
                         cudaFuncAttributeMaxDynamicSharedMemorySize, SM_TOT);
    dim3 grid(CE_S / TOK, 16);   // 16 x 16 = 256 CTAs
    conv_encoder_hmma<<<grid, THREADS, SM_TOT>>>(x, emb, bias, out);
}

// round 15
// speedup vs baseline: 1.0264x; 1.0264x over previous
#include <cuda_runtime.h>
#include <cuda_fp16.h>
#include <math.h>
#include <stdint.h>

// ConvEncoder: y = GELU(im2col(emb[x]) @ W^T + b).  M=32768, N=128, K=640.
// R15: R13 shape (single-pass fp16, tanh GELU, 8 warps of 64x64 tiles,
// 256 thr, TOK=256, 128 CTAs = 1 wave, 3-slot W ring) + DOUBLE-BUFFERED
// ldmatrix fragments: k-step s+1's LDSMs write the alternate register set,
// breaking the WAR dependency on k-step s's MMAs (the ~25us plateau).

#define CE_S    2048
#define CE_KTOT 640
#define THREADS 256
#define TOK     256
#define ROW_B   272                  // fp16 row: 256B data + 16B pad (A and W)

// smem layout (bytes)
#define SA      0                    // 260 rows * 272
#define SW_BASE 70720                // 3 slots x 34816 (128 rows * 272)
#define SW_SLOT 34816
#define SBIAS   175168
#define SIDX    175680               // 260 ints
#define SM_TOT  176768

// W pre-converted fp16: [kc(5)][o(128)][272B]
__device__ __align__(16) unsigned char g_Wcvt[5 * 128 * ROW_B];

// GELU, tanh form with HW MUFU tanh
__device__ __forceinline__ float gelu_fast(float x) {
    float t = x * fmaf(0.03567740814f, x * x, 0.79788456080f);
    float th;
    asm("tanh.approx.f32 %0, %1;" : "=f"(th) : "f"(t));
    float h = 0.5f * x;
    return fmaf(h, th, h);
}

__device__ __forceinline__ void mma_f16(float* c, const uint32_t* a, const uint32_t* b) {
    asm volatile(
        "mma.sync.aligned.m16n8k16.row.col.f32.f16.f16.f32 "
        "{%0,%1,%2,%3}, {%4,%5,%6,%7}, {%8,%9}, {%0,%1,%2,%3};"
        : "+f"(c[0]), "+f"(c[1]), "+f"(c[2]), "+f"(c[3])
        : "r"(a[0]), "r"(a[1]), "r"(a[2]), "r"(a[3]), "r"(b[0]), "r"(b[1]));
}

__device__ __forceinline__ void ldsm4(uint32_t* r, uint32_t addr) {
    asm volatile("ldmatrix.sync.aligned.m8n8.x4.shared.b16 {%0,%1,%2,%3}, [%4];"
                 : "=r"(r[0]), "=r"(r[1]), "=r"(r[2]), "=r"(r[3]) : "r"(addr));
}

__device__ __forceinline__ void cpasync16(uint32_t dst, const void* src) {
    asm volatile("cp.async.cg.shared.global [%0], [%1], 16;"
                 :: "r"(dst), "l"(src) : "memory");
}

// convert 8 f32 -> 8 fp16 packed as uint4 (16 bytes)
__device__ __forceinline__ uint4 cvt8_f16(float4 v0, float4 v1) {
    union { __half2 h[4]; uint4 u; } p;
    p.h[0] = __float22half2_rn(make_float2(v0.x, v0.y));
    p.h[1] = __float22half2_rn(make_float2(v0.z, v0.w));
    p.h[2] = __float22half2_rn(make_float2(v1.x, v1.y));
    p.h[3] = __float22half2_rn(make_float2(v1.z, v1.w));
    return p.u;
}

// ---- prep: W f32 -> fp16, chunked layout for direct cp.async ----
__global__ void __launch_bounds__(256)
prep_w_kernel(const float* __restrict__ W)
{
    int t = blockIdx.x * 256 + threadIdx.x;        // 5*128*16 = 10240 granules
    if (t >= 5 * 128 * 16) return;
    int gnl = t & 15;
    int o   = (t >> 4) & 127;
    int kc  = t >> 11;
    const float* src = W + (size_t)o * CE_KTOT + kc * 128 + gnl * 8;
    float4 v0 = *reinterpret_cast<const float4*>(src);
    float4 v1 = *reinterpret_cast<const float4*>(src + 4);
    *reinterpret_cast<uint4*>(g_Wcvt + ((size_t)kc * 128 + o) * ROW_B + gnl * 16)
        = cvt8_f16(v0, v1);
}

// stage one K=128 W chunk into a smem ring slot via cp.async
__device__ __forceinline__ void stage_w(uint32_t swdst, int kc, int tid) {
    const unsigned char* base = g_Wcvt + (size_t)kc * 128 * ROW_B;
    #pragma unroll
    for (int it = 0; it < 8; ++it) {
        int idx = tid + it * THREADS;              // 2048: 128 o x 16 granules
        int o = idx >> 4, gnl = idx & 15;
        cpasync16(swdst + o * ROW_B + gnl * 16,
                  base + (size_t)o * ROW_B + gnl * 16);
    }
}

__global__ void __launch_bounds__(THREADS)
conv_encoder_hmma(const int* __restrict__ x,
                  const float* __restrict__ emb,
                  const float* __restrict__ bias,
                  float* __restrict__ out)
{
    extern __shared__ uint8_t smem[];
    uint32_t sb;
    asm("{ .reg .u64 t; cvta.to.shared.u64 t, %1; cvt.u32.u64 %0, t; }"
        : "=r"(sb) : "l"(smem));

    const int tid = threadIdx.x;
    const int wid = tid >> 5;
    const int lid = tid & 31;
    const int g   = lid >> 2;
    const int q   = lid & 3;
    const int wm  = wid >> 1;       // 0..3  (64-row band within 256)
    const int wn  = wid & 1;        // 0..1  (64-col band)
    const int batch = blockIdx.y;
    const int s0 = blockIdx.x * TOK;

    // prefetch W chunks 0 and 1 (overlaps the A gather)
    stage_w(sb + SW_BASE, 0, tid);
    asm volatile("cp.async.commit_group;" ::: "memory");
    stage_w(sb + SW_BASE + SW_SLOT, 1, tid);
    asm volatile("cp.async.commit_group;" ::: "memory");

    if (tid < 32) {
        reinterpret_cast<float4*>(smem + SBIAS)[tid] =
            reinterpret_cast<const float4*>(bias)[tid];
    }
    // token index cache: halo rows p=0..259 -> seq s0+p-2 (or -1 if OOB)
    for (int p = tid; p < 260; p += THREADS) {
        int s = s0 + p - 2;
        reinterpret_cast<int*>(smem + SIDX)[p] =
            (s >= 0 && s < CE_S) ? x[batch * CE_S + s] : -1;
    }
    __syncthreads();

    // ---- stage halo'd A once: rows p=0..259, fp16 ----
    #pragma unroll
    for (int it = 0; it < 17; ++it) {
        int idx = tid + it * THREADS;              // 260*16 = 4160 tasks (32B each)
        if (idx < 260 * 16) {
            int p = idx >> 4;
            int c = idx & 15;                      // 16B fp16 granule = 8 elems
            int tok = reinterpret_cast<const int*>(smem + SIDX)[p];
            float4 v0 = make_float4(0.f, 0.f, 0.f, 0.f);
            float4 v1 = v0;
            if (tok >= 0) {
                const float* e = emb + (size_t)tok * 128 + c * 8;
                v0 = *reinterpret_cast<const float4*>(e);
                v1 = *reinterpret_cast<const float4*>(e + 4);
            }
            *reinterpret_cast<uint4*>(smem + SA + p * ROW_B + c * 16) = cvt8_f16(v0, v1);
        }
    }

    float acc[4][8][4];
    #pragma unroll
    for (int i = 0; i < 4; ++i)
        #pragma unroll
        for (int j = 0; j < 8; ++j)
            #pragma unroll
            for (int r = 0; r < 4; ++r)
                acc[i][j][r] = 0.f;

    // per-lane ldmatrix offsets
    const uint32_t a_off = ((lid & 7) + ((lid >> 3) & 1) * 8) * ROW_B + (lid >> 4) * 16;
    // B (x4, j-paired): lanes 0-15 -> n-tile 2jp (k halves), 16-31 -> n-tile 2jp+1
    const uint32_t b_off = ((lid & 7) + (lid >> 4) * 8) * ROW_B + ((lid >> 3) & 1) * 16;

    // double-buffered fragments: LDSMs of step s+1 write buffer !cur while
    // MMAs of step s read buffer cur -> no WAR stall on the frag registers.
    uint32_t Aa[2][4][4], Bp[2][4][4];

    #define LOAD_FRAGS(buf, base_a, base_b, kb) do {                      \
        ldsm4(Aa[buf][0], (base_a) + 0 * (16 * ROW_B) + (kb));            \
        ldsm4(Aa[buf][1], (base_a) + 1 * (16 * ROW_B) + (kb));            \
        ldsm4(Aa[buf][2], (base_a) + 2 * (16 * ROW_B) + (kb));            \
        ldsm4(Aa[buf][3], (base_a) + 3 * (16 * ROW_B) + (kb));            \
        ldsm4(Bp[buf][0], (base_b) + 0 * (16 * ROW_B) + (kb));            \
        ldsm4(Bp[buf][1], (base_b) + 1 * (16 * ROW_B) + (kb));            \
        ldsm4(Bp[buf][2], (base_b) + 2 * (16 * ROW_B) + (kb));            \
        ldsm4(Bp[buf][3], (base_b) + 3 * (16 * ROW_B) + (kb));            \
    } while (0)

    // ---- 5 chunks of K=128, 3-slot ring, ONE sync per chunk ----
    #pragma unroll
    for (int s = 0; s < 5; ++s) {
        if (s < 4) {
            asm volatile("cp.async.wait_group 1;" ::: "memory");
        } else {
            asm volatile("cp.async.wait_group 0;" ::: "memory");
        }
        __syncthreads();
        if (s < 3) {
            stage_w(sb + SW_BASE + ((s + 2) % 3) * SW_SLOT, s + 2, tid);
            asm volatile("cp.async.commit_group;" ::: "memory");
        }

        const uint32_t swb = sb + SW_BASE + (s % 3) * SW_SLOT;
        const uint32_t aA  = sb + SA + (wm * 64 + s) * ROW_B + a_off;
        const uint32_t aB  = swb + wn * 64 * ROW_B + b_off;

        LOAD_FRAGS(0, aA, aB, 0);
        #pragma unroll
        for (int ks = 0; ks < 8; ++ks) {
            const int cur = ks & 1;
            if (ks < 7)
                LOAD_FRAGS(cur ^ 1, aA, aB, (uint32_t)((ks + 1) * 32));
            #pragma unroll
            for (int i = 0; i < 4; ++i)
                #pragma unroll
                for (int j = 0; j < 8; ++j)
                    mma_f16(acc[i][j], Aa[cur][i], &Bp[cur][j >> 1][(j & 1) * 2]);
        }
    }
    #undef LOAD_FRAGS

    // ---- epilogue: bias + fast GELU + store ----
    const float* bs = reinterpret_cast<const float*>(smem + SBIAS);
    #pragma unroll
    for (int i = 0; i < 4; ++i) {
        int row0 = s0 + wm * 64 + i * 16 + g;
        #pragma unroll
        for (int j = 0; j < 8; ++j) {
            int col = wn * 64 + j * 8 + q * 2;
            float b0 = bs[col], b1 = bs[col + 1];
            float2 v0, v1;
            v0.x = gelu_fast(acc[i][j][0] + b0);
            v0.y = gelu_fast(acc[i][j][1] + b1);
            v1.x = gelu_fast(acc[i][j][2] + b0);
            v1.y = gelu_fast(acc[i][j][3] + b1);
            float* p0 = out + ((size_t)(batch * CE_S + row0)) * 128 + col;
            *reinterpret_cast<float2*>(p0) = v0;
            *reinterpret_cast<float2*>(p0 + 8 * 128) = v1;
        }
    }
}

extern "C" void kernel_launch(void* const* d_in, const int* in_sizes, int n_in,
                              void* d_out, int out_size)
{
    const int*   x    = (const int*)  d_in[0];
    const float* emb  = (const float*)d_in[1];
    const float* W    = (const float*)d_in[2];
    const float* bias = (const float*)d_in[3];
    float*       out  = (float*)d_out;

    prep_w_kernel<<<40, 256>>>(W);

    cudaFuncSetAttribute(conv_encoder_hmma,
                         cudaFuncAttributeMaxDynamicSharedMemorySize, SM_TOT);
    dim3 grid(CE_S / TOK, 16);   // 8 x 16 = 128 CTAs (one wave)
    conv_encoder_hmma<<<grid, THREADS, SM_TOT>>>(x, emb, bias, out);
}

// round 16
// speedup vs baseline: 1.0920x; 1.0639x over previous
#include <cuda_runtime.h>
#include <cuda_fp16.h>
#include <math.h>
#include <stdint.h>

// ConvEncoder: y = GELU(im2col(emb[x]) @ W^T + b).  M=32768, N=128, K=640.
// R16: single-pass fp16 + tanh GELU + 3-slot W ring (R10/R13 machinery),
// with a VIRTUAL PADDED token space: A'[b*2052 + r] = emb[x[b, r-2]] (0 in
// the 4-row inter-batch gap), so CTAs span batch seams. TOK=224 -> 147 CTAs
// = 99.3% SM fill in one wave (vs 128/148 = 86%).
// 448 threads, 14 warps as 7m x 2n, warp tile 32x64.

#define CE_S    2048
#define CE_KTOT 640
#define THREADS 448
#define TOK     224
#define VROW    2052                 // 2048 + 4 pad rows per batch
#define N_CTA   147                  // ceil((16*2052 - 4) / 224)
#define ROW_B   272                  // fp16 row: 256B data + 16B pad (A and W)

// smem layout (bytes)
#define SA      0                    // 228 rows * 272 = 62016
#define SW_BASE 62016                // 3 slots x 34816 (128 rows * 272)
#define SW_SLOT 34816
#define SBIAS   166464
#define SIDX    166976               // 228 ints
#define SM_TOT  167936

// W pre-converted fp16: [kc(5)][o(128)][272B]
__device__ __align__(16) unsigned char g_Wcvt[5 * 128 * ROW_B];

// GELU, tanh form with HW MUFU tanh
__device__ __forceinline__ float gelu_fast(float x) {
    float t = x * fmaf(0.03567740814f, x * x, 0.79788456080f);
    float th;
    asm("tanh.approx.f32 %0, %1;" : "=f"(th) : "f"(t));
    float h = 0.5f * x;
    return fmaf(h, th, h);
}

__device__ __forceinline__ void mma_f16(float* c, const uint32_t* a, const uint32_t* b) {
    asm volatile(
        "mma.sync.aligned.m16n8k16.row.col.f32.f16.f16.f32 "
        "{%0,%1,%2,%3}, {%4,%5,%6,%7}, {%8,%9}, {%0,%1,%2,%3};"
        : "+f"(c[0]), "+f"(c[1]), "+f"(c[2]), "+f"(c[3])
        : "r"(a[0]), "r"(a[1]), "r"(a[2]), "r"(a[3]), "r"(b[0]), "r"(b[1]));
}

__device__ __forceinline__ void ldsm4(uint32_t* r, uint32_t addr) {
    asm volatile("ldmatrix.sync.aligned.m8n8.x4.shared.b16 {%0,%1,%2,%3}, [%4];"
                 : "=r"(r[0]), "=r"(r[1]), "=r"(r[2]), "=r"(r[3]) : "r"(addr));
}

__device__ __forceinline__ void cpasync16(uint32_t dst, const void* src) {
    asm volatile("cp.async.cg.shared.global [%0], [%1], 16;"
                 :: "r"(dst), "l"(src) : "memory");
}

// convert 8 f32 -> 8 fp16 packed as uint4 (16 bytes)
__device__ __forceinline__ uint4 cvt8_f16(float4 v0, float4 v1) {
    union { __half2 h[4]; uint4 u; } p;
    p.h[0] = __float22half2_rn(make_float2(v0.x, v0.y));
    p.h[1] = __float22half2_rn(make_float2(v0.z, v0.w));
    p.h[2] = __float22half2_rn(make_float2(v1.x, v1.y));
    p.h[3] = __float22half2_rn(make_float2(v1.z, v1.w));
    return p.u;
}

// ---- prep: W f32 -> fp16, chunked layout for direct cp.async ----
__global__ void __launch_bounds__(256)
prep_w_kernel(const float* __restrict__ W)
{
    int t = blockIdx.x * 256 + threadIdx.x;        // 5*128*16 = 10240 granules
    if (t >= 5 * 128 * 16) return;
    int gnl = t & 15;
    int o   = (t >> 4) & 127;
    int kc  = t >> 11;
    const float* src = W + (size_t)o * CE_KTOT + kc * 128 + gnl * 8;
    float4 v0 = *reinterpret_cast<const float4*>(src);
    float4 v1 = *reinterpret_cast<const float4*>(src + 4);
    *reinterpret_cast<uint4*>(g_Wcvt + ((size_t)kc * 128 + o) * ROW_B + gnl * 16)
        = cvt8_f16(v0, v1);
}

// stage one K=128 W chunk into a smem ring slot via cp.async
__device__ __forceinline__ void stage_w(uint32_t swdst, int kc, int tid) {
    const unsigned char* base = g_Wcvt + (size_t)kc * 128 * ROW_B;
    #pragma unroll
    for (int it = 0; it < 5; ++it) {
        int idx = tid + it * THREADS;              // 2048: 128 o x 16 granules
        if (idx < 2048) {
            int o = idx >> 4, gnl = idx & 15;
            cpasync16(swdst + o * ROW_B + gnl * 16,
                      base + (size_t)o * ROW_B + gnl * 16);
        }
    }
}

__global__ void __launch_bounds__(THREADS)
conv_encoder_hmma(const int* __restrict__ x,
                  const float* __restrict__ emb,
                  const float* __restrict__ bias,
                  float* __restrict__ out)
{
    extern __shared__ uint8_t smem[];
    uint32_t sb;
    asm("{ .reg .u64 t; cvta.to.shared.u64 t, %1; cvt.u32.u64 %0, t; }"
        : "=r"(sb) : "l"(smem));

    const int tid = threadIdx.x;
    const int wid = tid >> 5;
    const int lid = tid & 31;
    const int g   = lid >> 2;
    const int q   = lid & 3;
    const int wm  = wid >> 1;       // 0..6  (32-row band within 224)
    const int wn  = wid & 1;        // 0..1  (64-col band)
    const int o0  = blockIdx.x * TOK;   // base of this CTA in virtual space

    // prefetch W chunks 0 and 1 (overlaps the A gather)
    stage_w(sb + SW_BASE, 0, tid);
    asm volatile("cp.async.commit_group;" ::: "memory");
    stage_w(sb + SW_BASE + SW_SLOT, 1, tid);
    asm volatile("cp.async.commit_group;" ::: "memory");

    if (tid < 32) {
        reinterpret_cast<float4*>(smem + SBIAS)[tid] =
            reinterpret_cast<const float4*>(bias)[tid];
    }
    // token index cache: halo rows p=0..227 -> virtual v = o0+p,
    // b = v/2052, r = v%2052; valid token iff r in [2,2050) and b < 16.
    for (int p = tid; p < TOK + 4; p += THREADS) {
        int v = o0 + p;
        int b = v / VROW;
        int r = v - b * VROW;
        int tok = -1;
        if (b < 16 && r >= 2 && r < 2050)
            tok = x[b * CE_S + (r - 2)];
        reinterpret_cast<int*>(smem + SIDX)[p] = tok;
    }
    __syncthreads();

    // ---- stage halo'd A: rows p=0..227, fp16 (228*16 = 3648 granules) ----
    #pragma unroll
    for (int it = 0; it < 9; ++it) {
        int idx = tid + it * THREADS;
        if (idx < (TOK + 4) * 16) {
            int p = idx >> 4;
            int c = idx & 15;                      // 16B fp16 granule = 8 elems
            int tok = reinterpret_cast<const int*>(smem + SIDX)[p];
            float4 v0 = make_float4(0.f, 0.f, 0.f, 0.f);
            float4 v1 = v0;
            if (tok >= 0) {
                const float* e = emb + (size_t)tok * 128 + c * 8;
                v0 = *reinterpret_cast<const float4*>(e);
                v1 = *reinterpret_cast<const float4*>(e + 4);
            }
            *reinterpret_cast<uint4*>(smem + SA + p * ROW_B + c * 16) = cvt8_f16(v0, v1);
        }
    }

    float acc[2][8][4];
    #pragma unroll
    for (int i = 0; i < 2; ++i)
        #pragma unroll
        for (int j = 0; j < 8; ++j)
            #pragma unroll
            for (int r = 0; r < 4; ++r)
                acc[i][j][r] = 0.f;

    // per-lane ldmatrix offsets
    const uint32_t a_off = ((lid & 7) + ((lid >> 3) & 1) * 8) * ROW_B + (lid >> 4) * 16;
    // B (x4, j-paired): lanes 0-15 -> n-tile 2jp (k halves), 16-31 -> 2jp+1
    const uint32_t b_off = ((lid & 7) + (lid >> 4) * 8) * ROW_B + ((lid >> 3) & 1) * 16;

    // ---- 5 chunks of K=128 (window offsets), 3-slot ring, one sync/chunk ----
    #pragma unroll
    for (int s = 0; s < 5; ++s) {
        if (s < 4) {
            asm volatile("cp.async.wait_group 1;" ::: "memory");
        } else {
            asm volatile("cp.async.wait_group 0;" ::: "memory");
        }
        __syncthreads();
        if (s < 3) {
            stage_w(sb + SW_BASE + ((s + 2) % 3) * SW_SLOT, s + 2, tid);
            asm volatile("cp.async.commit_group;" ::: "memory");
        }

        const uint32_t swb = sb + SW_BASE + (s % 3) * SW_SLOT;
        const uint32_t aA  = sb + SA + (wm * 32 + s) * ROW_B + a_off;
        const uint32_t aB  = swb + wn * 64 * ROW_B + b_off;

        #pragma unroll
        for (int ks = 0; ks < 8; ++ks) {
            const uint32_t kb = ks * 32;
            uint32_t Aa[2][4], Bp[4][4];
            #pragma unroll
            for (int i = 0; i < 2; ++i)
                ldsm4(Aa[i], aA + i * (16 * ROW_B) + kb);
            #pragma unroll
            for (int jp = 0; jp < 4; ++jp)
                ldsm4(Bp[jp], aB + jp * (16 * ROW_B) + kb);
            #pragma unroll
            for (int i = 0; i < 2; ++i)
                #pragma unroll
                for (int j = 0; j < 8; ++j)
                    mma_f16(acc[i][j], Aa[i], &Bp[j >> 1][(j & 1) * 2]);
        }
    }

    // ---- epilogue: bias + fast GELU + predicated store (skip pad rows) ----
    const float* bs = reinterpret_cast<const float*>(smem + SBIAS);
    #pragma unroll
    for (int i = 0; i < 2; ++i) {
        #pragma unroll
        for (int half = 0; half < 2; ++half) {      // frag rows g and g+8
            int op = o0 + wm * 32 + i * 16 + half * 8 + g;   // virtual token
            int b  = op / VROW;
            int sq = op - b * VROW;
            if (b < 16 && sq < CE_S) {
                float* orow = out + ((size_t)(b * CE_S + sq)) * 128;
                #pragma unroll
                for (int j = 0; j < 8; ++j) {
                    int col = wn * 64 + j * 8 + q * 2;
                    float2 v;
                    v.x = gelu_fast(acc[i][j][2 * half]     + bs[col]);
                    v.y = gelu_fast(acc[i][j][2 * half + 1] + bs[col + 1]);
                    *reinterpret_cast<float2*>(orow + col) = v;
                }
            }
        }
    }
}

extern "C" void kernel_launch(void* const* d_in, const int* in_sizes, int n_in,
                              void* d_out, int out_size)
{
    const int*   x    = (const int*)  d_in[0];
    const float* emb  = (const float*)d_in[1];
    const float* W    = (const float*)d_in[2];
    const float* bias = (const float*)d_in[3];
    float*       out  = (float*)d_out;

    prep_w_kernel<<<40, 256>>>(W);

    cudaFuncSetAttribute(conv_encoder_hmma,
                         cudaFuncAttributeMaxDynamicSharedMemorySize, SM_TOT);
    conv_encoder_hmma<<<N_CTA, THREADS, SM_TOT>>>(x, emb, bias, out);
}